// round 2
// baseline (speedup 1.0000x reference)
#include <cuda_runtime.h>

#define BATCH 4
#define SQ    4096
#define SKV   1024
#define DE    1024
#define DC    768
#define NH    16
#define DH    64

// Scratch (allocation-free rule: __device__ globals)
__device__ float g_Q[(size_t)BATCH * SQ * DE];
__device__ float g_K[(size_t)BATCH * SKV * DE];
__device__ float g_V[(size_t)BATCH * SKV * DE];
__device__ float g_Ctx[(size_t)BATCH * SQ * DE];

// ---------------------------------------------------------------------------
// f32x2 packed-FMA helpers (FFMA2 path: 2x fp32 throughput, exact fp32 math)
// ---------------------------------------------------------------------------
typedef unsigned long long ull;

__device__ __forceinline__ ull pack2(float lo, float hi) {
    ull r;
    asm("mov.b64 %0, {%1, %2};" : "=l"(r) : "f"(lo), "f"(hi));
    return r;
}
__device__ __forceinline__ float2 unpack2(ull v) {
    float2 f;
    asm("mov.b64 {%0, %1}, %2;" : "=f"(f.x), "=f"(f.y) : "l"(v));
    return f;
}
#define FMA2(d, a, b, c) \
    asm("fma.rn.f32x2 %0, %1, %2, %3;" : "=l"(d) : "l"(a), "l"(b), "l"(c))
#define MUL2(d, a, b) \
    asm("mul.rn.f32x2 %0, %1, %2;" : "=l"(d) : "l"(a), "l"(b))

// ---------------------------------------------------------------------------
// GEMM: C[M,N] = A[M,K] @ W[K,N] + bias[N]
// 128x128 tile, BK=16, 256 threads, 8x8 per thread, FFMA2 row-paired.
// ---------------------------------------------------------------------------
#define GBM 128
#define GBN 128
#define GBK 16
#define GTM 8
#define GTN 8

template <int MODE>
__global__ __launch_bounds__(256, 2)
void sgemm_bias(int M, int N, int K,
                const float* __restrict__ Ain,
                const float* __restrict__ W,
                const float* __restrict__ bias,
                float* __restrict__ Cout)
{
    const float* A = (MODE == 3) ? g_Ctx : Ain;
    float* C = (MODE == 0) ? g_Q : (MODE == 1) ? g_K : (MODE == 2) ? g_V : Cout;

    __shared__ __align__(16) float As[GBK][GBM + 4];  // transposed: As[k][m]
    __shared__ __align__(16) float Bs[GBK][GBN];

    const int tid = threadIdx.x;
    const int bx = blockIdx.x;
    const int by = blockIdx.y;

    A += (size_t)by * GBM * K;
    W += (size_t)bx * GBN;
    C += (size_t)by * GBM * N + (size_t)bx * GBN;
    const float* bptr = bias + (size_t)bx * GBN;

    const int aRow = tid >> 2;
    const int aCol = (tid & 3) << 2;
    const int bRow = tid >> 5;
    const int bCol = (tid & 31) << 2;

    const int tRow = (tid >> 4) * GTM;
    const int tCol = (tid & 15) * GTN;

    // acc2[ip][j] packs output rows (tRow+2ip, tRow+2ip+1) at column tCol+j
    ull acc2[GTM / 2][GTN] = {};

    for (int k0 = 0; k0 < K; k0 += GBK) {
        #pragma unroll
        for (int p = 0; p < 2; p++) {
            int r = aRow + p * 64;
            float4 v = *reinterpret_cast<const float4*>(A + (size_t)r * K + k0 + aCol);
            As[aCol + 0][r] = v.x;
            As[aCol + 1][r] = v.y;
            As[aCol + 2][r] = v.z;
            As[aCol + 3][r] = v.w;
        }
        #pragma unroll
        for (int p = 0; p < 2; p++) {
            int r = bRow + p * 8;
            *reinterpret_cast<float4*>(&Bs[r][bCol]) =
                *reinterpret_cast<const float4*>(W + (size_t)(k0 + r) * N + bCol);
        }
        __syncthreads();

        #pragma unroll
        for (int k = 0; k < GBK; k++) {
            const ulonglong2* ap =
                reinterpret_cast<const ulonglong2*>(&As[k][tRow]);
            ulonglong2 aA = ap[0];   // pairs (t0,t1),(t2,t3)
            ulonglong2 aB = ap[1];   // pairs (t4,t5),(t6,t7)
            ull am[4] = {aA.x, aA.y, aB.x, aB.y};

            float4 n0 = *reinterpret_cast<const float4*>(&Bs[k][tCol]);
            float4 n1 = *reinterpret_cast<const float4*>(&Bs[k][tCol + 4]);
            ull bb[8];
            bb[0] = pack2(n0.x, n0.x); bb[1] = pack2(n0.y, n0.y);
            bb[2] = pack2(n0.z, n0.z); bb[3] = pack2(n0.w, n0.w);
            bb[4] = pack2(n1.x, n1.x); bb[5] = pack2(n1.y, n1.y);
            bb[6] = pack2(n1.z, n1.z); bb[7] = pack2(n1.w, n1.w);

            #pragma unroll
            for (int ip = 0; ip < 4; ip++)
                #pragma unroll
                for (int j = 0; j < 8; j++)
                    FMA2(acc2[ip][j], am[ip], bb[j], acc2[ip][j]);
        }
        __syncthreads();
    }

    float4 bv0 = *reinterpret_cast<const float4*>(bptr + tCol);
    float4 bv1 = *reinterpret_cast<const float4*>(bptr + tCol + 4);
    float bv[8] = {bv0.x, bv0.y, bv0.z, bv0.w, bv1.x, bv1.y, bv1.z, bv1.w};

    #pragma unroll
    for (int ip = 0; ip < 4; ip++) {
        float lo[8], hi[8];
        #pragma unroll
        for (int j = 0; j < 8; j++) {
            float2 f = unpack2(acc2[ip][j]);
            lo[j] = f.x + bv[j];
            hi[j] = f.y + bv[j];
        }
        float* r0 = C + (size_t)(tRow + 2 * ip) * N + tCol;
        float* r1 = r0 + N;
        *reinterpret_cast<float4*>(r0)     = make_float4(lo[0], lo[1], lo[2], lo[3]);
        *reinterpret_cast<float4*>(r0 + 4) = make_float4(lo[4], lo[5], lo[6], lo[7]);
        *reinterpret_cast<float4*>(r1)     = make_float4(hi[0], hi[1], hi[2], hi[3]);
        *reinterpret_cast<float4*>(r1 + 4) = make_float4(hi[4], hi[5], hi[6], hi[7]);
    }
}

// ---------------------------------------------------------------------------
// Flash attention: Br=128 q-rows x Bc=64 kv per CTA, 256 threads, 8x4/thread.
// FFMA2 with row-paired accumulators; P tile chunk-XOR swizzled (bank-clean).
// Smem:
//   QsT[d][r]  d-major, stride 132  (S-GEMM A operand, row pairs contiguous)
//   KsT[d][c]  d-major, stride 68   (S-GEMM B operand)
//   Vs [c][d]  natural, stride 68   (PV B operand)
//   PsT[c][r]  c-major, stride 128, chunk swizzle: chunk(r/4) ^= (c>>2)&7
// ---------------------------------------------------------------------------
#define BR 128
#define BC 64
#define QSTR 132
#define KSTR 68
#define PSTR 128
#define SM_Q 0
#define SM_K (64 * QSTR)
#define SM_V (SM_K + 64 * KSTR)
#define SM_P (SM_V + 64 * KSTR)
#define ATT_SMEM_FLOATS (SM_P + 64 * PSTR)
#define ATT_SMEM_BYTES (ATT_SMEM_FLOATS * 4)   // 101376 B

__global__ __launch_bounds__(256, 1)
void flash_attn()
{
    extern __shared__ __align__(16) float sm[];
    float* QsT = sm + SM_Q;
    float* KsT = sm + SM_K;
    float* Vs  = sm + SM_V;
    float* PsT = sm + SM_P;

    const int tid = threadIdx.x;
    const int qb  = blockIdx.x;
    const int h   = blockIdx.y;
    const int b   = blockIdx.z;

    const float* Qg = g_Q   + ((size_t)b * SQ + (size_t)qb * BR) * DE + h * DH;
    const float* Kg = g_K   + (size_t)b * SKV * DE + h * DH;
    const float* Vg = g_V   + (size_t)b * SKV * DE + h * DH;
    float*       Og = g_Ctx + ((size_t)b * SQ + (size_t)qb * BR) * DE + h * DH;

    // Load Q tile (128x64), transpose to d-major, pre-apply 1/sqrt(64)
    #pragma unroll
    for (int p = 0; p < 8; p++) {
        int idx = tid + p * 256;
        int r = idx >> 4;            // 0..127
        int c = (idx & 15) << 2;     // 0..60
        float4 v = *reinterpret_cast<const float4*>(Qg + (size_t)r * DE + c);
        QsT[(c + 0) * QSTR + r] = v.x * 0.125f;
        QsT[(c + 1) * QSTR + r] = v.y * 0.125f;
        QsT[(c + 2) * QSTR + r] = v.z * 0.125f;
        QsT[(c + 3) * QSTR + r] = v.w * 0.125f;
    }

    const int ty = tid >> 4;
    const int tx = tid & 15;
    const int rowB = ty * 8;     // 8 q rows per thread
    const int colB = tx * 4;     // 4 kv cols per thread
    const int ech  = rowB >> 2;  // even chunk index of this thread's row block

    float m[8], l[8];
    ull o2[4][4];                // row pairs (rowB+2ip, rowB+2ip+1) x 4 d-cols
    #pragma unroll
    for (int i = 0; i < 8; i++) { m[i] = -1e30f; l[i] = 0.0f; }
    #pragma unroll
    for (int ip = 0; ip < 4; ip++)
        #pragma unroll
        for (int j = 0; j < 4; j++) o2[ip][j] = 0ull;

    for (int kv0 = 0; kv0 < SKV; kv0 += BC) {
        __syncthreads();  // prev PV reads (Vs, PsT) done; Q stores done (1st iter)
        #pragma unroll
        for (int p = 0; p < 4; p++) {
            int idx = tid + p * 256;
            int r = idx >> 4;            // kv row 0..63
            int c = (idx & 15) << 2;     // head-dim 0..60
            float4 kv = *reinterpret_cast<const float4*>(Kg + (size_t)(kv0 + r) * DE + c);
            KsT[(c + 0) * KSTR + r] = kv.x;
            KsT[(c + 1) * KSTR + r] = kv.y;
            KsT[(c + 2) * KSTR + r] = kv.z;
            KsT[(c + 3) * KSTR + r] = kv.w;
            *reinterpret_cast<float4*>(&Vs[r * KSTR + c]) =
                *reinterpret_cast<const float4*>(Vg + (size_t)(kv0 + r) * DE + c);
        }
        __syncthreads();

        // ---- S = Q K^T : 8x4 per thread, FFMA2 row-paired ----
        ull s2[4][4];
        #pragma unroll
        for (int ip = 0; ip < 4; ip++)
            #pragma unroll
            for (int j = 0; j < 4; j++) s2[ip][j] = 0ull;

        #pragma unroll 8
        for (int d = 0; d < DH; d++) {
            const ulonglong2* qp =
                reinterpret_cast<const ulonglong2*>(QsT + d * QSTR + rowB);
            ulonglong2 qa = qp[0];
            ulonglong2 qb2 = qp[1];
            ull qm[4] = {qa.x, qa.y, qb2.x, qb2.y};
            float4 k4 = *reinterpret_cast<const float4*>(KsT + d * KSTR + colB);
            ull kb[4];
            kb[0] = pack2(k4.x, k4.x); kb[1] = pack2(k4.y, k4.y);
            kb[2] = pack2(k4.z, k4.z); kb[3] = pack2(k4.w, k4.w);
            #pragma unroll
            for (int ip = 0; ip < 4; ip++)
                #pragma unroll
                for (int j = 0; j < 4; j++)
                    FMA2(s2[ip][j], qm[ip], kb[j], s2[ip][j]);
        }

        // ---- online softmax ----
        float s[8][4];
        #pragma unroll
        for (int ip = 0; ip < 4; ip++)
            #pragma unroll
            for (int j = 0; j < 4; j++) {
                float2 f = unpack2(s2[ip][j]);
                s[2 * ip + 0][j] = f.x;
                s[2 * ip + 1][j] = f.y;
            }

        float corr[8];
        #pragma unroll
        for (int i = 0; i < 8; i++) {
            float rm = fmaxf(fmaxf(s[i][0], s[i][1]), fmaxf(s[i][2], s[i][3]));
            rm = fmaxf(rm, __shfl_xor_sync(0xffffffffu, rm, 1));
            rm = fmaxf(rm, __shfl_xor_sync(0xffffffffu, rm, 2));
            rm = fmaxf(rm, __shfl_xor_sync(0xffffffffu, rm, 4));
            rm = fmaxf(rm, __shfl_xor_sync(0xffffffffu, rm, 8));
            float mn = fmaxf(m[i], rm);
            corr[i] = __expf(m[i] - mn);
            m[i] = mn;
            float rs = 0.0f;
            #pragma unroll
            for (int j = 0; j < 4; j++) {
                s[i][j] = __expf(s[i][j] - mn);
                rs += s[i][j];
            }
            rs += __shfl_xor_sync(0xffffffffu, rs, 1);
            rs += __shfl_xor_sync(0xffffffffu, rs, 2);
            rs += __shfl_xor_sync(0xffffffffu, rs, 4);
            rs += __shfl_xor_sync(0xffffffffu, rs, 8);
            l[i] = l[i] * corr[i] + rs;
        }

        // rescale running output (packed)
        #pragma unroll
        for (int ip = 0; ip < 4; ip++) {
            ull cp = pack2(corr[2 * ip], corr[2 * ip + 1]);
            #pragma unroll
            for (int j = 0; j < 4; j++)
                MUL2(o2[ip][j], o2[ip][j], cp);
        }

        // ---- store P (c-major, chunk-swizzled, conflict-free float4 stores) ----
        #pragma unroll
        for (int j = 0; j < 4; j++) {
            int c = colB + j;
            int sw = (c >> 2) & 7;
            float* pb = PsT + c * PSTR;
            *reinterpret_cast<float4*>(pb + 4 * (ech ^ sw)) =
                make_float4(s[0][j], s[1][j], s[2][j], s[3][j]);
            *reinterpret_cast<float4*>(pb + 4 * ((ech + 1) ^ sw)) =
                make_float4(s[4][j], s[5][j], s[6][j], s[7][j]);
        }
        __syncthreads();

        // ---- O += P V : FFMA2 row-paired ----
        #pragma unroll 8
        for (int c = 0; c < BC; c++) {
            int sw = (c >> 2) & 7;
            const float* pb = PsT + c * PSTR;
            ulonglong2 pa =
                *reinterpret_cast<const ulonglong2*>(pb + 4 * (ech ^ sw));
            ulonglong2 pc =
                *reinterpret_cast<const ulonglong2*>(pb + 4 * ((ech + 1) ^ sw));
            ull pm[4] = {pa.x, pa.y, pc.x, pc.y};
            float4 v4 = *reinterpret_cast<const float4*>(Vs + c * KSTR + colB);
            ull vb[4];
            vb[0] = pack2(v4.x, v4.x); vb[1] = pack2(v4.y, v4.y);
            vb[2] = pack2(v4.z, v4.z); vb[3] = pack2(v4.w, v4.w);
            #pragma unroll
            for (int ip = 0; ip < 4; ip++)
                #pragma unroll
                for (int j = 0; j < 4; j++)
                    FMA2(o2[ip][j], pm[ip], vb[j], o2[ip][j]);
        }
    }

    // normalize + write ctx
    #pragma unroll
    for (int ip = 0; ip < 4; ip++) {
        float inv0 = 1.0f / l[2 * ip + 0];
        float inv1 = 1.0f / l[2 * ip + 1];
        float r0[4], r1[4];
        #pragma unroll
        for (int j = 0; j < 4; j++) {
            float2 f = unpack2(o2[ip][j]);
            r0[j] = f.x * inv0;
            r1[j] = f.y * inv1;
        }
        float* o0 = Og + (size_t)(rowB + 2 * ip) * DE + colB;
        *reinterpret_cast<float4*>(o0)      = make_float4(r0[0], r0[1], r0[2], r0[3]);
        *reinterpret_cast<float4*>(o0 + DE) = make_float4(r1[0], r1[1], r1[2], r1[3]);
    }
}

// ---------------------------------------------------------------------------
extern "C" void kernel_launch(void* const* d_in, const int* in_sizes, int n_in,
                              void* d_out, int out_size)
{
    const float* x  = (const float*)d_in[0];
    const float* y  = (const float*)d_in[1];
    const float* Wq = (const float*)d_in[2];
    const float* bq = (const float*)d_in[3];
    const float* Wk = (const float*)d_in[4];
    const float* bk = (const float*)d_in[5];
    const float* Wv = (const float*)d_in[6];
    const float* bv = (const float*)d_in[7];
    const float* Wo = (const float*)d_in[8];
    const float* bo = (const float*)d_in[9];
    float* out = (float*)d_out;

    (void)in_sizes; (void)n_in; (void)out_size;

    sgemm_bias<0><<<dim3(DE / GBN, (BATCH * SQ) / GBM), 256>>>(
        BATCH * SQ, DE, DE, x, Wq, bq, nullptr);
    sgemm_bias<1><<<dim3(DE / GBN, (BATCH * SKV) / GBM), 256>>>(
        BATCH * SKV, DE, DC, y, Wk, bk, nullptr);
    sgemm_bias<2><<<dim3(DE / GBN, (BATCH * SKV) / GBM), 256>>>(
        BATCH * SKV, DE, DC, y, Wv, bv, nullptr);

    cudaFuncSetAttribute(flash_attn, cudaFuncAttributeMaxDynamicSharedMemorySize,
                         ATT_SMEM_BYTES);
    flash_attn<<<dim3(SQ / BR, NH, BATCH), 256, ATT_SMEM_BYTES>>>();

    sgemm_bias<3><<<dim3(DE / GBN, (BATCH * SQ) / GBM), 256>>>(
        BATCH * SQ, DE, DE, nullptr, Wo, bo, out);
}

// round 5
// speedup vs baseline: 2.0720x; 2.0720x over previous
#include <cuda_runtime.h>
#include <cuda_bf16.h>
#include <cstdint>

#define BATCH 4
#define SQ    4096
#define SKV   1024
#define DE    1024
#define DC    768
#define NH    16
#define DH    64
#define MQ    (BATCH * SQ)    // 16384
#define MKV   (BATCH * SKV)   // 4096

// ---------------- scratch (__device__ globals; no runtime alloc) -----------
__device__ float g_Q[(size_t)MQ * DE];
__device__ float g_K[(size_t)MKV * DE];
__device__ float g_V[(size_t)MKV * DE];
__device__ float g_Ctx[(size_t)MQ * DE];

__device__ __align__(16) __nv_bfloat16 g_xh[(size_t)MQ * DE];
__device__ __align__(16) __nv_bfloat16 g_xl[(size_t)MQ * DE];
__device__ __align__(16) __nv_bfloat16 g_yh[(size_t)MKV * DC];
__device__ __align__(16) __nv_bfloat16 g_yl[(size_t)MKV * DC];
__device__ __align__(16) __nv_bfloat16 g_ch[(size_t)MQ * DE];
__device__ __align__(16) __nv_bfloat16 g_cl[(size_t)MQ * DE];
__device__ __align__(16) __nv_bfloat16 g_Wqh[(size_t)DE * DE];
__device__ __align__(16) __nv_bfloat16 g_Wql[(size_t)DE * DE];
__device__ __align__(16) __nv_bfloat16 g_Wkh[(size_t)DE * DC];
__device__ __align__(16) __nv_bfloat16 g_Wkl[(size_t)DE * DC];
__device__ __align__(16) __nv_bfloat16 g_Wvh[(size_t)DE * DC];
__device__ __align__(16) __nv_bfloat16 g_Wvl[(size_t)DE * DC];
__device__ __align__(16) __nv_bfloat16 g_Woh[(size_t)DE * DE];
__device__ __align__(16) __nv_bfloat16 g_Wol[(size_t)DE * DE];

// ---------------- PTX helpers (sm_103-safe: NO tcgen05) --------------------
__device__ __forceinline__ uint32_t smem_u32(const void* p) {
    uint32_t a;
    asm("{ .reg .u64 t; cvta.to.shared.u64 t, %1; cvt.u32.u64 %0, t; }"
        : "=r"(a) : "l"(p));
    return a;
}
__device__ __forceinline__ void cp16(uint32_t dst, const void* src) {
    asm volatile("cp.async.cg.shared.global [%0], [%1], 16;"
                 :: "r"(dst), "l"(src) : "memory");
}
#define CP_COMMIT() asm volatile("cp.async.commit_group;" ::: "memory")
#define CP_WAIT1()  asm volatile("cp.async.wait_group 1;" ::: "memory")
#define CP_WAIT0()  asm volatile("cp.async.wait_group 0;" ::: "memory")

#define LDSM4(r0, r1, r2, r3, addr) \
    asm volatile("ldmatrix.sync.aligned.m8n8.x4.shared.b16 {%0,%1,%2,%3}, [%4];" \
                 : "=r"(r0), "=r"(r1), "=r"(r2), "=r"(r3) : "r"(addr))

#define MMA16816(d, a, b) \
    asm volatile("mma.sync.aligned.m16n8k16.row.col.f32.bf16.bf16.f32 " \
                 "{%0,%1,%2,%3},{%4,%5,%6,%7},{%8,%9},{%0,%1,%2,%3};" \
                 : "+f"((d)[0]), "+f"((d)[1]), "+f"((d)[2]), "+f"((d)[3]) \
                 : "r"((a)[0]), "r"((a)[1]), "r"((a)[2]), "r"((a)[3]), \
                   "r"((b)[0]), "r"((b)[1]))

// ---------------- conversion kernels ---------------------------------------
__global__ void k_split(const float* __restrict__ in,
                        __nv_bfloat16* __restrict__ hi,
                        __nv_bfloat16* __restrict__ lo, int n4)
{
    int i = blockIdx.x * blockDim.x + threadIdx.x;
    if (i >= n4) return;
    float4 v = reinterpret_cast<const float4*>(in)[i];
    __nv_bfloat16 h0 = __float2bfloat16(v.x);
    __nv_bfloat16 h1 = __float2bfloat16(v.y);
    __nv_bfloat16 h2 = __float2bfloat16(v.z);
    __nv_bfloat16 h3 = __float2bfloat16(v.w);
    __nv_bfloat16 l0 = __float2bfloat16(v.x - __bfloat162float(h0));
    __nv_bfloat16 l1 = __float2bfloat16(v.y - __bfloat162float(h1));
    __nv_bfloat16 l2 = __float2bfloat16(v.z - __bfloat162float(h2));
    __nv_bfloat16 l3 = __float2bfloat16(v.w - __bfloat162float(h3));
    reinterpret_cast<__nv_bfloat162*>(hi)[2 * i]     = __nv_bfloat162(h0, h1);
    reinterpret_cast<__nv_bfloat162*>(hi)[2 * i + 1] = __nv_bfloat162(h2, h3);
    reinterpret_cast<__nv_bfloat162*>(lo)[2 * i]     = __nv_bfloat162(l0, l1);
    reinterpret_cast<__nv_bfloat162*>(lo)[2 * i + 1] = __nv_bfloat162(l2, l3);
}

// W[K,N] -> Wt hi/lo [N,K]
__global__ void k_tsplit(const float* __restrict__ W,
                         __nv_bfloat16* __restrict__ th,
                         __nv_bfloat16* __restrict__ tl, int Kd, int Nd)
{
    __shared__ float t[32][33];
    int n0 = blockIdx.x * 32, k0 = blockIdx.y * 32;
    int tx = threadIdx.x, ty = threadIdx.y;
    #pragma unroll
    for (int i = 0; i < 32; i += 8)
        t[ty + i][tx] = W[(size_t)(k0 + ty + i) * Nd + n0 + tx];
    __syncthreads();
    #pragma unroll
    for (int i = 0; i < 32; i += 8) {
        float v = t[tx][ty + i];
        __nv_bfloat16 h = __float2bfloat16(v);
        size_t o = (size_t)(n0 + ty + i) * Kd + k0 + tx;
        th[o] = h;
        tl[o] = __float2bfloat16(v - __bfloat162float(h));
    }
}

// ---------------- warp-mma split-bf16 GEMM ----------------------------------
// C[M, DE] = A[M,K] * Bt[DE,K]^T + bias, via Ah*Bh + Ah*Bl + Al*Bh (fp32 accum)
// CTA 128x128, BK=64. 8 warps (2m x 4n), warp tile 64x32.
// smem rows: 64 bf16 = 128B, 8 x 16B chunks, swizzle chunk ^= (row & 7).
#define BM 128
#define BN 128
#define BK 64
#define OFF_AH 0
#define OFF_AL 16384
#define OFF_BH 32768
#define OFF_BL 49152
#define STAGE 65536
#define GEMM_SMEM (2 * STAGE)

__global__ __launch_bounds__(256, 1)
void gemm_mma(int M, int K,
              const __nv_bfloat16* __restrict__ Ah, const __nv_bfloat16* __restrict__ Al,
              const __nv_bfloat16* __restrict__ Bh, const __nv_bfloat16* __restrict__ Bl,
              const float* __restrict__ bias, float* __restrict__ C)
{
    extern __shared__ __align__(128) char dsm[];
    const uint32_t sb = smem_u32(dsm);

    const int tid  = threadIdx.x;
    const int wid  = tid >> 5;
    const int lane = tid & 31;
    const int n0 = blockIdx.x * BN;
    const int m0 = blockIdx.y * BM;
    const int NC = K / BK;

    const int warp_m = (wid & 1) * 64;
    const int warp_n = (wid >> 1) * 32;

    float d[4][4][4];
    #pragma unroll
    for (int i = 0; i < 4; i++)
        #pragma unroll
        for (int j = 0; j < 4; j++)
            #pragma unroll
            for (int e = 0; e < 4; e++) d[i][j][e] = 0.0f;

    // ---- stage loader: 128 rows x 8 chunks for each of AH/AL/BH/BL ----
    auto load_stage = [&](int buf, int kc) {
        uint32_t base = sb + (uint32_t)buf * STAGE;
        int k0 = kc * BK;
        #pragma unroll
        for (int t = 0; t < 4; t++) {               // A: 1024 chunk-slots
            int idx = tid + t * 256;
            int row = idx >> 3, ch = idx & 7;
            uint32_t sw = (uint32_t)(row * 128 + 16 * (ch ^ (row & 7)));
            size_t g = (size_t)(m0 + row) * K + k0 + ch * 8;
            cp16(base + OFF_AH + sw, Ah + g);
            cp16(base + OFF_AL + sw, Al + g);
        }
        #pragma unroll
        for (int t = 0; t < 4; t++) {               // B: 1024 chunk-slots
            int idx = tid + t * 256;
            int row = idx >> 3, ch = idx & 7;
            uint32_t sw = (uint32_t)(row * 128 + 16 * (ch ^ (row & 7)));
            size_t g = (size_t)(n0 + row) * K + k0 + ch * 8;
            cp16(base + OFF_BH + sw, Bh + g);
            cp16(base + OFF_BL + sw, Bl + g);
        }
        CP_COMMIT();
    };

    // ldmatrix lane-address components (row within tile, chunk-bit)
    const int aRowL = warp_m + (lane & 7) + ((lane >> 3) & 1) * 8;  // + 16*i
    const int aCbit = (lane >> 4);                                   // chunk +0/1
    const int bRowL = warp_n + (lane & 7) + ((lane >> 4) & 1) * 8;  // + 16*j2
    const int bCbit = (lane >> 3) & 1;

    load_stage(0, 0);

    for (int c = 0; c < NC; c++) {
        if (c + 1 < NC) { load_stage((c + 1) & 1, c + 1); CP_WAIT1(); }
        else            { CP_WAIT0(); }
        __syncthreads();

        uint32_t base = sb + (uint32_t)(c & 1) * STAGE;

        #pragma unroll
        for (int ks = 0; ks < 4; ks++) {
            uint32_t ah[4][4], al[4][4], bh[4][2], bl[4][2];

            #pragma unroll
            for (int i = 0; i < 4; i++) {
                int row = aRowL + 16 * i;
                uint32_t off = (uint32_t)(row * 128 +
                               16 * ((2 * ks + aCbit) ^ (row & 7)));
                LDSM4(ah[i][0], ah[i][1], ah[i][2], ah[i][3], base + OFF_AH + off);
                LDSM4(al[i][0], al[i][1], al[i][2], al[i][3], base + OFF_AL + off);
            }
            #pragma unroll
            for (int j2 = 0; j2 < 2; j2++) {
                int row = bRowL + 16 * j2;
                uint32_t off = (uint32_t)(row * 128 +
                               16 * ((2 * ks + bCbit) ^ (row & 7)));
                LDSM4(bh[2 * j2][0], bh[2 * j2][1], bh[2 * j2 + 1][0], bh[2 * j2 + 1][1],
                      base + OFF_BH + off);
                LDSM4(bl[2 * j2][0], bl[2 * j2][1], bl[2 * j2 + 1][0], bl[2 * j2 + 1][1],
                      base + OFF_BL + off);
            }
            #pragma unroll
            for (int i = 0; i < 4; i++)
                #pragma unroll
                for (int j = 0; j < 4; j++) {
                    MMA16816(d[i][j], ah[i], bh[j]);
                    MMA16816(d[i][j], ah[i], bl[j]);
                    MMA16816(d[i][j], al[i], bh[j]);
                }
        }
        __syncthreads();
    }

    // ---- epilogue: fragment -> global with bias ----
    const int frow = lane >> 2;          // 0..7
    const int fcol = (lane & 3) * 2;     // 0,2,4,6
    #pragma unroll
    for (int j = 0; j < 4; j++) {
        int col = n0 + warp_n + 8 * j + fcol;
        float b0 = bias[col], b1 = bias[col + 1];
        #pragma unroll
        for (int i = 0; i < 4; i++) {
            int row = m0 + warp_m + 16 * i + frow;
            float2 v0 = make_float2(d[i][j][0] + b0, d[i][j][1] + b1);
            float2 v1 = make_float2(d[i][j][2] + b0, d[i][j][3] + b1);
            *reinterpret_cast<float2*>(C + (size_t)row * DE + col)       = v0;
            *reinterpret_cast<float2*>(C + (size_t)(row + 8) * DE + col) = v1;
        }
    }
}

// ---------------- flash attention (R1 version, known good) -----------------
#define ASTRIDE 68
#define ATT_SMEM_BYTES (4 * 64 * ASTRIDE * 4)

__global__ __launch_bounds__(256)
void flash_attn()
{
    extern __shared__ __align__(16) float sm[];
    float* QsT = sm;
    float* KsT = sm + 1 * 64 * ASTRIDE;
    float* Vs  = sm + 2 * 64 * ASTRIDE;
    float* PsT = sm + 3 * 64 * ASTRIDE;

    const int tid = threadIdx.x;
    const int qb  = blockIdx.x;
    const int h   = blockIdx.y;
    const int b   = blockIdx.z;

    const float* Qg = g_Q   + ((size_t)b * SQ + qb * 64) * DE + h * DH;
    const float* Kg = g_K   + (size_t)b * SKV * DE + h * DH;
    const float* Vg = g_V   + (size_t)b * SKV * DE + h * DH;
    float*       Og = g_Ctx + ((size_t)b * SQ + qb * 64) * DE + h * DH;

    #pragma unroll
    for (int p = 0; p < 4; p++) {
        int idx = tid + p * 256;
        int r = idx >> 4;
        int c = (idx & 15) << 2;
        float4 v = *reinterpret_cast<const float4*>(Qg + (size_t)r * DE + c);
        QsT[(c + 0) * ASTRIDE + r] = v.x * 0.125f;
        QsT[(c + 1) * ASTRIDE + r] = v.y * 0.125f;
        QsT[(c + 2) * ASTRIDE + r] = v.z * 0.125f;
        QsT[(c + 3) * ASTRIDE + r] = v.w * 0.125f;
    }

    const int ty = tid >> 4;
    const int tx = tid & 15;
    const int rowB = ty * 4;
    const int colB = tx * 4;

    float m[4], l[4], o[4][4];
    #pragma unroll
    for (int i = 0; i < 4; i++) {
        m[i] = -1e30f;
        l[i] = 0.0f;
        #pragma unroll
        for (int j = 0; j < 4; j++) o[i][j] = 0.0f;
    }

    for (int kv0 = 0; kv0 < SKV; kv0 += 64) {
        __syncthreads();
        #pragma unroll
        for (int p = 0; p < 4; p++) {
            int idx = tid + p * 256;
            int r = idx >> 4;
            int c = (idx & 15) << 2;
            float4 kv = *reinterpret_cast<const float4*>(Kg + (size_t)(kv0 + r) * DE + c);
            KsT[(c + 0) * ASTRIDE + r] = kv.x;
            KsT[(c + 1) * ASTRIDE + r] = kv.y;
            KsT[(c + 2) * ASTRIDE + r] = kv.z;
            KsT[(c + 3) * ASTRIDE + r] = kv.w;
            *reinterpret_cast<float4*>(&Vs[r * ASTRIDE + c]) =
                *reinterpret_cast<const float4*>(Vg + (size_t)(kv0 + r) * DE + c);
        }
        __syncthreads();

        float s[4][4] = {};
        #pragma unroll 16
        for (int dd = 0; dd < 64; dd++) {
            float4 q4 = *reinterpret_cast<const float4*>(QsT + dd * ASTRIDE + rowB);
            float4 k4 = *reinterpret_cast<const float4*>(KsT + dd * ASTRIDE + colB);
            float qv[4] = {q4.x, q4.y, q4.z, q4.w};
            float kw[4] = {k4.x, k4.y, k4.z, k4.w};
            #pragma unroll
            for (int i = 0; i < 4; i++)
                #pragma unroll
                for (int j = 0; j < 4; j++)
                    s[i][j] = fmaf(qv[i], kw[j], s[i][j]);
        }

        #pragma unroll
        for (int i = 0; i < 4; i++) {
            float rm = fmaxf(fmaxf(s[i][0], s[i][1]), fmaxf(s[i][2], s[i][3]));
            rm = fmaxf(rm, __shfl_xor_sync(0xffffffffu, rm, 1));
            rm = fmaxf(rm, __shfl_xor_sync(0xffffffffu, rm, 2));
            rm = fmaxf(rm, __shfl_xor_sync(0xffffffffu, rm, 4));
            rm = fmaxf(rm, __shfl_xor_sync(0xffffffffu, rm, 8));
            float mn = fmaxf(m[i], rm);
            float corr = __expf(m[i] - mn);
            m[i] = mn;
            float rs = 0.0f;
            #pragma unroll
            for (int j = 0; j < 4; j++) {
                s[i][j] = __expf(s[i][j] - mn);
                rs += s[i][j];
            }
            rs += __shfl_xor_sync(0xffffffffu, rs, 1);
            rs += __shfl_xor_sync(0xffffffffu, rs, 2);
            rs += __shfl_xor_sync(0xffffffffu, rs, 4);
            rs += __shfl_xor_sync(0xffffffffu, rs, 8);
            l[i] = l[i] * corr + rs;
            #pragma unroll
            for (int j = 0; j < 4; j++) o[i][j] *= corr;
        }

        #pragma unroll
        for (int i = 0; i < 4; i++)
            #pragma unroll
            for (int j = 0; j < 4; j++)
                PsT[(colB + j) * ASTRIDE + rowB + i] = s[i][j];
        __syncthreads();

        #pragma unroll 16
        for (int cc = 0; cc < 64; cc++) {
            float4 p4 = *reinterpret_cast<const float4*>(PsT + cc * ASTRIDE + rowB);
            float4 v4 = *reinterpret_cast<const float4*>(Vs  + cc * ASTRIDE + colB);
            float pv[4] = {p4.x, p4.y, p4.z, p4.w};
            float vv[4] = {v4.x, v4.y, v4.z, v4.w};
            #pragma unroll
            for (int i = 0; i < 4; i++)
                #pragma unroll
                for (int j = 0; j < 4; j++)
                    o[i][j] = fmaf(pv[i], vv[j], o[i][j]);
        }
    }

    #pragma unroll
    for (int i = 0; i < 4; i++) {
        float inv = 1.0f / l[i];
        float4 v;
        v.x = o[i][0] * inv;
        v.y = o[i][1] * inv;
        v.z = o[i][2] * inv;
        v.w = o[i][3] * inv;
        *reinterpret_cast<float4*>(Og + (size_t)(rowB + i) * DE + colB) = v;
    }
}

// ---------------------------------------------------------------------------
extern "C" void kernel_launch(void* const* d_in, const int* in_sizes, int n_in,
                              void* d_out, int out_size)
{
    const float* x  = (const float*)d_in[0];
    const float* y  = (const float*)d_in[1];
    const float* Wq = (const float*)d_in[2];
    const float* bq = (const float*)d_in[3];
    const float* Wk = (const float*)d_in[4];
    const float* bk = (const float*)d_in[5];
    const float* Wv = (const float*)d_in[6];
    const float* bv = (const float*)d_in[7];
    const float* Wo = (const float*)d_in[8];
    const float* bo = (const float*)d_in[9];
    float* out = (float*)d_out;
    (void)in_sizes; (void)n_in; (void)out_size;

    float *pQ, *pK, *pV, *pCx;
    cudaGetSymbolAddress((void**)&pQ,  g_Q);
    cudaGetSymbolAddress((void**)&pK,  g_K);
    cudaGetSymbolAddress((void**)&pV,  g_V);
    cudaGetSymbolAddress((void**)&pCx, g_Ctx);
    __nv_bfloat16 *pxh, *pxl, *pyh, *pyl, *pch, *pcl;
    __nv_bfloat16 *pWqh, *pWql, *pWkh, *pWkl, *pWvh, *pWvl, *pWoh, *pWol;
    cudaGetSymbolAddress((void**)&pxh,  g_xh);
    cudaGetSymbolAddress((void**)&pxl,  g_xl);
    cudaGetSymbolAddress((void**)&pyh,  g_yh);
    cudaGetSymbolAddress((void**)&pyl,  g_yl);
    cudaGetSymbolAddress((void**)&pch,  g_ch);
    cudaGetSymbolAddress((void**)&pcl,  g_cl);
    cudaGetSymbolAddress((void**)&pWqh, g_Wqh);
    cudaGetSymbolAddress((void**)&pWql, g_Wql);
    cudaGetSymbolAddress((void**)&pWkh, g_Wkh);
    cudaGetSymbolAddress((void**)&pWkl, g_Wkl);
    cudaGetSymbolAddress((void**)&pWvh, g_Wvh);
    cudaGetSymbolAddress((void**)&pWvl, g_Wvl);
    cudaGetSymbolAddress((void**)&pWoh, g_Woh);
    cudaGetSymbolAddress((void**)&pWol, g_Wol);

    cudaFuncSetAttribute(gemm_mma, cudaFuncAttributeMaxDynamicSharedMemorySize, GEMM_SMEM);
    cudaFuncSetAttribute(flash_attn, cudaFuncAttributeMaxDynamicSharedMemorySize,
                         ATT_SMEM_BYTES);

    // split activations + weights
    k_split<<<(MQ * DE / 4 + 255) / 256, 256>>>(x, pxh, pxl, MQ * DE / 4);
    k_split<<<(MKV * DC / 4 + 255) / 256, 256>>>(y, pyh, pyl, MKV * DC / 4);
    k_tsplit<<<dim3(DE / 32, DE / 32), dim3(32, 8)>>>(Wq, pWqh, pWql, DE, DE);
    k_tsplit<<<dim3(DE / 32, DC / 32), dim3(32, 8)>>>(Wk, pWkh, pWkl, DC, DE);
    k_tsplit<<<dim3(DE / 32, DC / 32), dim3(32, 8)>>>(Wv, pWvh, pWvl, DC, DE);
    k_tsplit<<<dim3(DE / 32, DE / 32), dim3(32, 8)>>>(Wo, pWoh, pWol, DE, DE);

    // projections (warp-mma bf16 split)
    gemm_mma<<<dim3(DE / BN, MQ / BM), 256, GEMM_SMEM>>>(MQ, DE, pxh, pxl, pWqh, pWql, bq, pQ);
    gemm_mma<<<dim3(DE / BN, MKV / BM), 256, GEMM_SMEM>>>(MKV, DC, pyh, pyl, pWkh, pWkl, bk, pK);
    gemm_mma<<<dim3(DE / BN, MKV / BM), 256, GEMM_SMEM>>>(MKV, DC, pyh, pyl, pWvh, pWvl, bv, pV);

    // attention (fp32 SIMT, R1)
    flash_attn<<<dim3(SQ / 64, NH, BATCH), 256, ATT_SMEM_BYTES>>>();

    // output projection
    k_split<<<(MQ * DE / 4 + 255) / 256, 256>>>(pCx, pch, pcl, MQ * DE / 4);
    gemm_mma<<<dim3(DE / BN, MQ / BM), 256, GEMM_SMEM>>>(MQ, DE, pch, pcl, pWoh, pWol, bo, out);
}

// round 6
// speedup vs baseline: 4.5371x; 2.1897x over previous
#include <cuda_runtime.h>
#include <cuda_bf16.h>
#include <cstdint>

#define BATCH 4
#define SQ    4096
#define SKV   1024
#define DE    1024
#define DC    768
#define NH    16
#define DH    64
#define MQ    (BATCH * SQ)    // 16384
#define MKV   (BATCH * SKV)   // 4096

// ---------------- scratch (__device__ globals; no runtime alloc) -----------
__device__ __align__(16) __nv_bfloat16 g_xh[(size_t)MQ * DE];
__device__ __align__(16) __nv_bfloat16 g_xl[(size_t)MQ * DE];
__device__ __align__(16) __nv_bfloat16 g_yh[(size_t)MKV * DC];
__device__ __align__(16) __nv_bfloat16 g_yl[(size_t)MKV * DC];
__device__ __align__(16) __nv_bfloat16 g_Qh[(size_t)MQ * DE];
__device__ __align__(16) __nv_bfloat16 g_Ql[(size_t)MQ * DE];
__device__ __align__(16) __nv_bfloat16 g_Kh[(size_t)MKV * DE];
__device__ __align__(16) __nv_bfloat16 g_Kl[(size_t)MKV * DE];
__device__ __align__(16) __nv_bfloat16 g_Vh[(size_t)MKV * DE];
__device__ __align__(16) __nv_bfloat16 g_Vl[(size_t)MKV * DE];
__device__ __align__(16) __nv_bfloat16 g_ch[(size_t)MQ * DE];
__device__ __align__(16) __nv_bfloat16 g_cl[(size_t)MQ * DE];
__device__ __align__(16) __nv_bfloat16 g_Wqh[(size_t)DE * DE];
__device__ __align__(16) __nv_bfloat16 g_Wql[(size_t)DE * DE];
__device__ __align__(16) __nv_bfloat16 g_Wkh[(size_t)DE * DC];
__device__ __align__(16) __nv_bfloat16 g_Wkl[(size_t)DE * DC];
__device__ __align__(16) __nv_bfloat16 g_Wvh[(size_t)DE * DC];
__device__ __align__(16) __nv_bfloat16 g_Wvl[(size_t)DE * DC];
__device__ __align__(16) __nv_bfloat16 g_Woh[(size_t)DE * DE];
__device__ __align__(16) __nv_bfloat16 g_Wol[(size_t)DE * DE];

// ---------------- PTX helpers (sm_103-safe: NO tcgen05) --------------------
__device__ __forceinline__ uint32_t smem_u32(const void* p) {
    uint32_t a;
    asm("{ .reg .u64 t; cvta.to.shared.u64 t, %1; cvt.u32.u64 %0, t; }"
        : "=r"(a) : "l"(p));
    return a;
}
__device__ __forceinline__ void cp16(uint32_t dst, const void* src) {
    asm volatile("cp.async.cg.shared.global [%0], [%1], 16;"
                 :: "r"(dst), "l"(src) : "memory");
}
#define CP_COMMIT() asm volatile("cp.async.commit_group;" ::: "memory")
#define CP_WAIT1()  asm volatile("cp.async.wait_group 1;" ::: "memory")
#define CP_WAIT0()  asm volatile("cp.async.wait_group 0;" ::: "memory")

#define LDSM4(r0, r1, r2, r3, addr) \
    asm volatile("ldmatrix.sync.aligned.m8n8.x4.shared.b16 {%0,%1,%2,%3}, [%4];" \
                 : "=r"(r0), "=r"(r1), "=r"(r2), "=r"(r3) : "r"(addr))
#define LDSM4T(r0, r1, r2, r3, addr) \
    asm volatile("ldmatrix.sync.aligned.m8n8.x4.trans.shared.b16 {%0,%1,%2,%3}, [%4];" \
                 : "=r"(r0), "=r"(r1), "=r"(r2), "=r"(r3) : "r"(addr))

#define MMA16816(d, a, b) \
    asm volatile("mma.sync.aligned.m16n8k16.row.col.f32.bf16.bf16.f32 " \
                 "{%0,%1,%2,%3},{%4,%5,%6,%7},{%8,%9},{%0,%1,%2,%3};" \
                 : "+f"((d)[0]), "+f"((d)[1]), "+f"((d)[2]), "+f"((d)[3]) \
                 : "r"((a)[0]), "r"((a)[1]), "r"((a)[2]), "r"((a)[3]), \
                   "r"((b)[0]), "r"((b)[1]))

__device__ __forceinline__ void split_pair(float f0, float f1,
                                           uint32_t& h, uint32_t& l) {
    __nv_bfloat162 hb = __floats2bfloat162_rn(f0, f1);   // .x = f0 (low)
    float r0 = f0 - __low2float(hb);
    float r1 = f1 - __high2float(hb);
    __nv_bfloat162 lb = __floats2bfloat162_rn(r0, r1);
    h = reinterpret_cast<uint32_t&>(hb);
    l = reinterpret_cast<uint32_t&>(lb);
}

// ---------------- conversion kernels ---------------------------------------
__global__ void k_split(const float* __restrict__ in,
                        __nv_bfloat16* __restrict__ hi,
                        __nv_bfloat16* __restrict__ lo, int n4)
{
    int i = blockIdx.x * blockDim.x + threadIdx.x;
    if (i >= n4) return;
    float4 v = reinterpret_cast<const float4*>(in)[i];
    __nv_bfloat16 h0 = __float2bfloat16(v.x);
    __nv_bfloat16 h1 = __float2bfloat16(v.y);
    __nv_bfloat16 h2 = __float2bfloat16(v.z);
    __nv_bfloat16 h3 = __float2bfloat16(v.w);
    __nv_bfloat16 l0 = __float2bfloat16(v.x - __bfloat162float(h0));
    __nv_bfloat16 l1 = __float2bfloat16(v.y - __bfloat162float(h1));
    __nv_bfloat16 l2 = __float2bfloat16(v.z - __bfloat162float(h2));
    __nv_bfloat16 l3 = __float2bfloat16(v.w - __bfloat162float(h3));
    reinterpret_cast<__nv_bfloat162*>(hi)[2 * i]     = __nv_bfloat162(h0, h1);
    reinterpret_cast<__nv_bfloat162*>(hi)[2 * i + 1] = __nv_bfloat162(h2, h3);
    reinterpret_cast<__nv_bfloat162*>(lo)[2 * i]     = __nv_bfloat162(l0, l1);
    reinterpret_cast<__nv_bfloat162*>(lo)[2 * i + 1] = __nv_bfloat162(l2, l3);
}

// W[K,N] -> Wt hi/lo [N,K]
__global__ void k_tsplit(const float* __restrict__ W,
                         __nv_bfloat16* __restrict__ th,
                         __nv_bfloat16* __restrict__ tl, int Kd, int Nd)
{
    __shared__ float t[32][33];
    int n0 = blockIdx.x * 32, k0 = blockIdx.y * 32;
    int tx = threadIdx.x, ty = threadIdx.y;
    #pragma unroll
    for (int i = 0; i < 32; i += 8)
        t[ty + i][tx] = W[(size_t)(k0 + ty + i) * Nd + n0 + tx];
    __syncthreads();
    #pragma unroll
    for (int i = 0; i < 32; i += 8) {
        float v = t[tx][ty + i];
        __nv_bfloat16 h = __float2bfloat16(v);
        size_t o = (size_t)(n0 + ty + i) * Kd + k0 + tx;
        th[o] = h;
        tl[o] = __float2bfloat16(v - __bfloat162float(h));
    }
}

// ---------------- warp-mma split-bf16 GEMM ----------------------------------
// OUTM 0: C fp32 (+bias). OUTM 1: Ch/Cl bf16 hi/lo of (acc+bias)*scale.
#define BM 128
#define BN 128
#define BK 64
#define OFF_AH 0
#define OFF_AL 16384
#define OFF_BH 32768
#define OFF_BL 49152
#define STAGE 65536
#define GEMM_SMEM (2 * STAGE)

template <int OUTM>
__global__ __launch_bounds__(256, 1)
void gemm_mma(int M, int K,
              const __nv_bfloat16* __restrict__ Ah, const __nv_bfloat16* __restrict__ Al,
              const __nv_bfloat16* __restrict__ Bh, const __nv_bfloat16* __restrict__ Bl,
              const float* __restrict__ bias, float scale,
              float* __restrict__ C,
              __nv_bfloat16* __restrict__ Ch, __nv_bfloat16* __restrict__ Cl)
{
    extern __shared__ __align__(128) char dsm[];
    const uint32_t sb = smem_u32(dsm);

    const int tid  = threadIdx.x;
    const int wid  = tid >> 5;
    const int lane = tid & 31;
    const int n0 = blockIdx.x * BN;
    const int m0 = blockIdx.y * BM;
    const int NC = K / BK;

    const int warp_m = (wid & 1) * 64;
    const int warp_n = (wid >> 1) * 32;

    float d[4][4][4];
    #pragma unroll
    for (int i = 0; i < 4; i++)
        #pragma unroll
        for (int j = 0; j < 4; j++)
            #pragma unroll
            for (int e = 0; e < 4; e++) d[i][j][e] = 0.0f;

    auto load_stage = [&](int buf, int kc) {
        uint32_t base = sb + (uint32_t)buf * STAGE;
        int k0 = kc * BK;
        #pragma unroll
        for (int t = 0; t < 4; t++) {
            int idx = tid + t * 256;
            int row = idx >> 3, ch = idx & 7;
            uint32_t sw = (uint32_t)(row * 128 + 16 * (ch ^ (row & 7)));
            size_t g = (size_t)(m0 + row) * K + k0 + ch * 8;
            cp16(base + OFF_AH + sw, Ah + g);
            cp16(base + OFF_AL + sw, Al + g);
        }
        #pragma unroll
        for (int t = 0; t < 4; t++) {
            int idx = tid + t * 256;
            int row = idx >> 3, ch = idx & 7;
            uint32_t sw = (uint32_t)(row * 128 + 16 * (ch ^ (row & 7)));
            size_t g = (size_t)(n0 + row) * K + k0 + ch * 8;
            cp16(base + OFF_BH + sw, Bh + g);
            cp16(base + OFF_BL + sw, Bl + g);
        }
        CP_COMMIT();
    };

    const int aRowL = warp_m + (lane & 7) + ((lane >> 3) & 1) * 8;
    const int aCbit = (lane >> 4);
    const int bRowL = warp_n + (lane & 7) + ((lane >> 4) & 1) * 8;
    const int bCbit = (lane >> 3) & 1;

    load_stage(0, 0);

    for (int c = 0; c < NC; c++) {
        if (c + 1 < NC) { load_stage((c + 1) & 1, c + 1); CP_WAIT1(); }
        else            { CP_WAIT0(); }
        __syncthreads();

        uint32_t base = sb + (uint32_t)(c & 1) * STAGE;

        #pragma unroll
        for (int ks = 0; ks < 4; ks++) {
            uint32_t ah[4][4], al[4][4], bh[4][2], bl[4][2];
            #pragma unroll
            for (int i = 0; i < 4; i++) {
                int row = aRowL + 16 * i;
                uint32_t off = (uint32_t)(row * 128 +
                               16 * ((2 * ks + aCbit) ^ (row & 7)));
                LDSM4(ah[i][0], ah[i][1], ah[i][2], ah[i][3], base + OFF_AH + off);
                LDSM4(al[i][0], al[i][1], al[i][2], al[i][3], base + OFF_AL + off);
            }
            #pragma unroll
            for (int j2 = 0; j2 < 2; j2++) {
                int row = bRowL + 16 * j2;
                uint32_t off = (uint32_t)(row * 128 +
                               16 * ((2 * ks + bCbit) ^ (row & 7)));
                LDSM4(bh[2 * j2][0], bh[2 * j2][1], bh[2 * j2 + 1][0], bh[2 * j2 + 1][1],
                      base + OFF_BH + off);
                LDSM4(bl[2 * j2][0], bl[2 * j2][1], bl[2 * j2 + 1][0], bl[2 * j2 + 1][1],
                      base + OFF_BL + off);
            }
            #pragma unroll
            for (int i = 0; i < 4; i++)
                #pragma unroll
                for (int j = 0; j < 4; j++) {
                    MMA16816(d[i][j], ah[i], bh[j]);
                    MMA16816(d[i][j], ah[i], bl[j]);
                    MMA16816(d[i][j], al[i], bh[j]);
                }
        }
        __syncthreads();
    }

    const int frow = lane >> 2;
    const int fcol = (lane & 3) * 2;
    #pragma unroll
    for (int j = 0; j < 4; j++) {
        int col = n0 + warp_n + 8 * j + fcol;
        float b0 = bias[col], b1 = bias[col + 1];
        #pragma unroll
        for (int i = 0; i < 4; i++) {
            int row = m0 + warp_m + 16 * i + frow;
            if (OUTM == 0) {
                float2 v0 = make_float2(d[i][j][0] + b0, d[i][j][1] + b1);
                float2 v1 = make_float2(d[i][j][2] + b0, d[i][j][3] + b1);
                *reinterpret_cast<float2*>(C + (size_t)row * DE + col)       = v0;
                *reinterpret_cast<float2*>(C + (size_t)(row + 8) * DE + col) = v1;
            } else {
                uint32_t h, l;
                split_pair((d[i][j][0] + b0) * scale, (d[i][j][1] + b1) * scale, h, l);
                *reinterpret_cast<uint32_t*>(Ch + (size_t)row * DE + col) = h;
                *reinterpret_cast<uint32_t*>(Cl + (size_t)row * DE + col) = l;
                split_pair((d[i][j][2] + b0) * scale, (d[i][j][3] + b1) * scale, h, l);
                *reinterpret_cast<uint32_t*>(Ch + (size_t)(row + 8) * DE + col) = h;
                *reinterpret_cast<uint32_t*>(Cl + (size_t)(row + 8) * DE + col) = l;
            }
        }
    }
}

// ---------------- flash attention via mma.sync (split bf16) -----------------
// CTA: 128 q rows x one (b,h). 8 warps x m16. 64-kv chunks, double buffered.
#define FBR 128
#define FBC 64
#define FNCH (SKV / FBC)
#define SQH 0
#define SQL 16384
#define SKV0 32768
#define SK_H 0
#define SK_L 8192
#define SV_H 16384
#define SV_L 24576
#define FSTG 32768
#define FLASH_SMEM (SKV0 + 2 * FSTG)   // 98304

__global__ __launch_bounds__(256, 1)
void flash_mma()
{
    extern __shared__ __align__(128) char fsm[];
    const uint32_t sb = smem_u32(fsm);
    const int tid = threadIdx.x, wid = tid >> 5, lane = tid & 31;
    const int qb = blockIdx.x, h = blockIdx.y, b = blockIdx.z;

    const size_t qrow0 = (size_t)b * SQ + (size_t)qb * FBR;
    const size_t krow0 = (size_t)b * SKV;
    const int colh = h * DH;

    // initial: Q (hi/lo) + KV stage 0
    #pragma unroll
    for (int t = 0; t < 4; t++) {
        int idx = tid + t * 256;
        int row = idx >> 3, ch = idx & 7;
        uint32_t sw = (uint32_t)(row * 128 + 16 * (ch ^ (row & 7)));
        size_t g = (qrow0 + row) * DE + colh + ch * 8;
        cp16(sb + SQH + sw, g_Qh + g);
        cp16(sb + SQL + sw, g_Ql + g);
    }
    #pragma unroll
    for (int t = 0; t < 2; t++) {
        int idx = tid + t * 256;
        int row = idx >> 3, ch = idx & 7;
        uint32_t sw = (uint32_t)(row * 128 + 16 * (ch ^ (row & 7)));
        size_t g = (krow0 + row) * DE + colh + ch * 8;
        cp16(sb + SKV0 + SK_H + sw, g_Kh + g);
        cp16(sb + SKV0 + SK_L + sw, g_Kl + g);
        cp16(sb + SKV0 + SV_H + sw, g_Vh + g);
        cp16(sb + SKV0 + SV_L + sw, g_Vl + g);
    }
    CP_COMMIT();
    CP_WAIT0();
    __syncthreads();

    // Q fragments (register resident)
    const int aRow = wid * 16 + (lane & 7) + ((lane >> 3) & 1) * 8;
    const int aC = (lane >> 4) & 1;
    uint32_t qh[4][4], ql[4][4];
    #pragma unroll
    for (int ks = 0; ks < 4; ks++) {
        uint32_t off = (uint32_t)(aRow * 128 + 16 * ((2 * ks + aC) ^ (aRow & 7)));
        LDSM4(qh[ks][0], qh[ks][1], qh[ks][2], qh[ks][3], sb + SQH + off);
        LDSM4(ql[ks][0], ql[ks][1], ql[ks][2], ql[ks][3], sb + SQL + off);
    }

    const int bRow = (lane & 7) + ((lane >> 4) & 1) * 8;   // K n-rows
    const int bC = (lane >> 3) & 1;
    const int vRow = (lane & 7) + ((lane >> 3) & 1) * 8;   // V kv-rows (trans)
    const int vC = (lane >> 4) & 1;

    float m0 = -1e30f, m1 = -1e30f, l0 = 0.0f, l1 = 0.0f;
    float o[8][4];
    #pragma unroll
    for (int j = 0; j < 8; j++)
        #pragma unroll
        for (int e = 0; e < 4; e++) o[j][e] = 0.0f;

    for (int c = 0; c < FNCH; c++) {
        uint32_t stg = sb + SKV0 + (uint32_t)(c & 1) * FSTG;
        if (c + 1 < FNCH) {
            uint32_t nst = sb + SKV0 + (uint32_t)((c + 1) & 1) * FSTG;
            #pragma unroll
            for (int t = 0; t < 2; t++) {
                int idx = tid + t * 256;
                int row = idx >> 3, ch = idx & 7;
                uint32_t sw = (uint32_t)(row * 128 + 16 * (ch ^ (row & 7)));
                size_t g = (krow0 + (size_t)(c + 1) * FBC + row) * DE + colh + ch * 8;
                cp16(nst + SK_H + sw, g_Kh + g);
                cp16(nst + SK_L + sw, g_Kl + g);
                cp16(nst + SV_H + sw, g_Vh + g);
                cp16(nst + SV_L + sw, g_Vl + g);
            }
            CP_COMMIT();
        }

        // ---- S = Q K^T (3-term split) ----
        float s[8][4];
        #pragma unroll
        for (int j = 0; j < 8; j++)
            #pragma unroll
            for (int e = 0; e < 4; e++) s[j][e] = 0.0f;

        #pragma unroll
        for (int ks = 0; ks < 4; ks++) {
            uint32_t kh[8][2], kl[8][2];
            #pragma unroll
            for (int np = 0; np < 4; np++) {
                int row = np * 16 + bRow;
                uint32_t off = (uint32_t)(row * 128 + 16 * ((2 * ks + bC) ^ (row & 7)));
                LDSM4(kh[2 * np][0], kh[2 * np][1], kh[2 * np + 1][0], kh[2 * np + 1][1],
                      stg + SK_H + off);
                LDSM4(kl[2 * np][0], kl[2 * np][1], kl[2 * np + 1][0], kl[2 * np + 1][1],
                      stg + SK_L + off);
            }
            #pragma unroll
            for (int j = 0; j < 8; j++) {
                MMA16816(s[j], qh[ks], kh[j]);
                MMA16816(s[j], qh[ks], kl[j]);
                MMA16816(s[j], ql[ks], kh[j]);
            }
        }

        // ---- online softmax (rows r0 = lane>>2, r1 = r0+8) ----
        float rm0 = -1e30f, rm1 = -1e30f;
        #pragma unroll
        for (int j = 0; j < 8; j++) {
            rm0 = fmaxf(rm0, fmaxf(s[j][0], s[j][1]));
            rm1 = fmaxf(rm1, fmaxf(s[j][2], s[j][3]));
        }
        rm0 = fmaxf(rm0, __shfl_xor_sync(0xffffffffu, rm0, 1));
        rm0 = fmaxf(rm0, __shfl_xor_sync(0xffffffffu, rm0, 2));
        rm1 = fmaxf(rm1, __shfl_xor_sync(0xffffffffu, rm1, 1));
        rm1 = fmaxf(rm1, __shfl_xor_sync(0xffffffffu, rm1, 2));

        float nm0 = fmaxf(m0, rm0), nm1 = fmaxf(m1, rm1);
        float cr0 = __expf(m0 - nm0), cr1 = __expf(m1 - nm1);
        m0 = nm0; m1 = nm1;

        float rs0 = 0.0f, rs1 = 0.0f;
        #pragma unroll
        for (int j = 0; j < 8; j++) {
            s[j][0] = __expf(s[j][0] - m0);
            s[j][1] = __expf(s[j][1] - m0);
            s[j][2] = __expf(s[j][2] - m1);
            s[j][3] = __expf(s[j][3] - m1);
            rs0 += s[j][0] + s[j][1];
            rs1 += s[j][2] + s[j][3];
        }
        rs0 += __shfl_xor_sync(0xffffffffu, rs0, 1);
        rs0 += __shfl_xor_sync(0xffffffffu, rs0, 2);
        rs1 += __shfl_xor_sync(0xffffffffu, rs1, 1);
        rs1 += __shfl_xor_sync(0xffffffffu, rs1, 2);
        l0 = l0 * cr0 + rs0;
        l1 = l1 * cr1 + rs1;

        #pragma unroll
        for (int j = 0; j < 8; j++) {
            o[j][0] *= cr0; o[j][1] *= cr0;
            o[j][2] *= cr1; o[j][3] *= cr1;
        }

        // ---- P -> bf16 hi/lo A-fragments (register repack, no smem) ----
        uint32_t ph[4][4], pl[4][4];
        #pragma unroll
        for (int ks = 0; ks < 4; ks++) {
            split_pair(s[2 * ks][0],     s[2 * ks][1],     ph[ks][0], pl[ks][0]);
            split_pair(s[2 * ks][2],     s[2 * ks][3],     ph[ks][1], pl[ks][1]);
            split_pair(s[2 * ks + 1][0], s[2 * ks + 1][1], ph[ks][2], pl[ks][2]);
            split_pair(s[2 * ks + 1][2], s[2 * ks + 1][3], ph[ks][3], pl[ks][3]);
        }

        // ---- O += P V (3-term, V via ldmatrix.trans) ----
        #pragma unroll
        for (int ks = 0; ks < 4; ks++) {
            uint32_t vh[8][2], vl[8][2];
            #pragma unroll
            for (int dp = 0; dp < 4; dp++) {
                int row = ks * 16 + vRow;
                uint32_t off = (uint32_t)(row * 128 + 16 * ((2 * dp + vC) ^ (row & 7)));
                LDSM4T(vh[2 * dp][0], vh[2 * dp][1], vh[2 * dp + 1][0], vh[2 * dp + 1][1],
                       stg + SV_H + off);
                LDSM4T(vl[2 * dp][0], vl[2 * dp][1], vl[2 * dp + 1][0], vl[2 * dp + 1][1],
                       stg + SV_L + off);
            }
            #pragma unroll
            for (int j = 0; j < 8; j++) {
                MMA16816(o[j], ph[ks], vh[j]);
                MMA16816(o[j], ph[ks], vl[j]);
                MMA16816(o[j], pl[ks], vh[j]);
            }
        }

        if (c + 1 < FNCH) CP_WAIT0();
        __syncthreads();
    }

    // ---- epilogue: ctx bf16 hi/lo ----
    float inv0 = 1.0f / l0, inv1 = 1.0f / l1;
    size_t r0g = (qrow0 + wid * 16 + (lane >> 2)) * DE + colh;
    size_t r1g = r0g + (size_t)8 * DE;
    #pragma unroll
    for (int j = 0; j < 8; j++) {
        int col = 8 * j + (lane & 3) * 2;
        uint32_t hh, ll;
        split_pair(o[j][0] * inv0, o[j][1] * inv0, hh, ll);
        *reinterpret_cast<uint32_t*>(g_ch + r0g + col) = hh;
        *reinterpret_cast<uint32_t*>(g_cl + r0g + col) = ll;
        split_pair(o[j][2] * inv1, o[j][3] * inv1, hh, ll);
        *reinterpret_cast<uint32_t*>(g_ch + r1g + col) = hh;
        *reinterpret_cast<uint32_t*>(g_cl + r1g + col) = ll;
    }
}

// ---------------------------------------------------------------------------
extern "C" void kernel_launch(void* const* d_in, const int* in_sizes, int n_in,
                              void* d_out, int out_size)
{
    const float* x  = (const float*)d_in[0];
    const float* y  = (const float*)d_in[1];
    const float* Wq = (const float*)d_in[2];
    const float* bq = (const float*)d_in[3];
    const float* Wk = (const float*)d_in[4];
    const float* bk = (const float*)d_in[5];
    const float* Wv = (const float*)d_in[6];
    const float* bv = (const float*)d_in[7];
    const float* Wo = (const float*)d_in[8];
    const float* bo = (const float*)d_in[9];
    float* out = (float*)d_out;
    (void)in_sizes; (void)n_in; (void)out_size;

    __nv_bfloat16 *pxh, *pxl, *pyh, *pyl, *pch, *pcl;
    __nv_bfloat16 *pQh, *pQl, *pKh, *pKl, *pVh, *pVl;
    __nv_bfloat16 *pWqh, *pWql, *pWkh, *pWkl, *pWvh, *pWvl, *pWoh, *pWol;
    cudaGetSymbolAddress((void**)&pxh,  g_xh);
    cudaGetSymbolAddress((void**)&pxl,  g_xl);
    cudaGetSymbolAddress((void**)&pyh,  g_yh);
    cudaGetSymbolAddress((void**)&pyl,  g_yl);
    cudaGetSymbolAddress((void**)&pch,  g_ch);
    cudaGetSymbolAddress((void**)&pcl,  g_cl);
    cudaGetSymbolAddress((void**)&pQh,  g_Qh);
    cudaGetSymbolAddress((void**)&pQl,  g_Ql);
    cudaGetSymbolAddress((void**)&pKh,  g_Kh);
    cudaGetSymbolAddress((void**)&pKl,  g_Kl);
    cudaGetSymbolAddress((void**)&pVh,  g_Vh);
    cudaGetSymbolAddress((void**)&pVl,  g_Vl);
    cudaGetSymbolAddress((void**)&pWqh, g_Wqh);
    cudaGetSymbolAddress((void**)&pWql, g_Wql);
    cudaGetSymbolAddress((void**)&pWkh, g_Wkh);
    cudaGetSymbolAddress((void**)&pWkl, g_Wkl);
    cudaGetSymbolAddress((void**)&pWvh, g_Wvh);
    cudaGetSymbolAddress((void**)&pWvl, g_Wvl);
    cudaGetSymbolAddress((void**)&pWoh, g_Woh);
    cudaGetSymbolAddress((void**)&pWol, g_Wol);

    cudaFuncSetAttribute(gemm_mma<0>, cudaFuncAttributeMaxDynamicSharedMemorySize, GEMM_SMEM);
    cudaFuncSetAttribute(gemm_mma<1>, cudaFuncAttributeMaxDynamicSharedMemorySize, GEMM_SMEM);
    cudaFuncSetAttribute(flash_mma, cudaFuncAttributeMaxDynamicSharedMemorySize, FLASH_SMEM);

    // split inputs
    k_split<<<(MQ * DE / 4 + 255) / 256, 256>>>(x, pxh, pxl, MQ * DE / 4);
    k_split<<<(MKV * DC / 4 + 255) / 256, 256>>>(y, pyh, pyl, MKV * DC / 4);
    k_tsplit<<<dim3(DE / 32, DE / 32), dim3(32, 8)>>>(Wq, pWqh, pWql, DE, DE);
    k_tsplit<<<dim3(DE / 32, DC / 32), dim3(32, 8)>>>(Wk, pWkh, pWkl, DC, DE);
    k_tsplit<<<dim3(DE / 32, DC / 32), dim3(32, 8)>>>(Wv, pWvh, pWvl, DC, DE);
    k_tsplit<<<dim3(DE / 32, DE / 32), dim3(32, 8)>>>(Wo, pWoh, pWol, DE, DE);

    // projections -> bf16 hi/lo directly (Q pre-scaled by 1/sqrt(dh))
    gemm_mma<1><<<dim3(DE / BN, MQ / BM), 256, GEMM_SMEM>>>(
        MQ, DE, pxh, pxl, pWqh, pWql, bq, 0.125f, nullptr, pQh, pQl);
    gemm_mma<1><<<dim3(DE / BN, MKV / BM), 256, GEMM_SMEM>>>(
        MKV, DC, pyh, pyl, pWkh, pWkl, bk, 1.0f, nullptr, pKh, pKl);
    gemm_mma<1><<<dim3(DE / BN, MKV / BM), 256, GEMM_SMEM>>>(
        MKV, DC, pyh, pyl, pWvh, pWvl, bv, 1.0f, nullptr, pVh, pVl);

    // attention (tensor-core, split bf16) -> ctx bf16 hi/lo
    flash_mma<<<dim3(SQ / FBR, NH, BATCH), 256, FLASH_SMEM>>>();

    // output projection -> fp32 out
    gemm_mma<0><<<dim3(DE / BN, MQ / BM), 256, GEMM_SMEM>>>(
        MQ, DE, pch, pcl, pWoh, pWol, bo, 1.0f, out, nullptr, nullptr);
}